// round 16
// baseline (speedup 1.0000x reference)
#include <cuda_runtime.h>

// ---------------------------------------------------------------------------
// CubicHermite2d — two-pass cubic Hermite (dx = 1).
//   result = h00*y[I] + h10*m[I] + h01*y[I+1] + h11*m[I+1]
//   m[0] = y1-y0; m[N-1] = y[N-1]-y[N-2]; m[i] = 0.5*(y[i+1]-y[i-1])
//   I = clamp(ceil(v)-1, 0, N-2)   == searchsorted(x0[1:-1], v, 'left')
// pass1: R11 structure, but slopes m[] are computed ONCE per row into a
//        separate scalar smem array (reference's own formulas) so each eval
//        is 4 scalar LDS + 4 FMA — no clamps, no edge selects. One query
//        per thread (R15's float2/pairing pathologies removed).
// pass2: R11-proven — warp-uniform SHIFT dedup over sorted qy
//        (d in {0,1,2,else}), P2_G=16 chain, __stcs stores.
// ---------------------------------------------------------------------------

#define TMP_ELEMS (32u * 512u * 1024u)   // B*H*Nx intermediate [B*H, Nx]
#define P1_ROWS 8
#define P1_WMAX 512
#define P1_QCH  1024
#define P2_G    16

__device__ float g_tmp[TMP_ELEMS];

__device__ __forceinline__ void hermite_h(float v, int N, int* Iout, float4* hout) {
    int I = (int)ceilf(v) - 1;          // searchsorted-left on arange
    I = max(0, min(I, N - 2));
    float t  = v - (float)I;
    float t2 = t * t;
    float t3 = t2 * t;
    *Iout = I;
    *hout = make_float4(1.0f - 3.0f * t2 + 2.0f * t3,   // h00
                        t - 2.0f * t2 + t3,             // h10
                        3.0f * t2 - 2.0f * t3,          // h01
                        t3 - t2);                       // h11
}

// Pass 1: block = P1_ROWS consecutive (b,h) rows in smem as scalar y[] and
// m[] arrays; query weights computed once per block into smem.
__global__ __launch_bounds__(256) void k_pass1(const float* __restrict__ sig,
                                               const float* __restrict__ xs,
                                               int W, int Nx, int nRows) {
    __shared__ float  s_y[P1_ROWS][P1_WMAX + 1];
    __shared__ float  s_m[P1_ROWS][P1_WMAX + 1];
    __shared__ int    s_ix[P1_QCH];
    __shared__ float4 s_hx[P1_QCH];

    const int tid   = threadIdx.x;
    const int rows0 = blockIdx.x * P1_ROWS;
    const int rcnt  = min(P1_ROWS, nRows - rows0);

    if (W <= P1_WMAX) {
        // Stage y.
        for (int idx = tid; idx < rcnt * W; idx += 256) {
            int r = idx / W, c = idx - r * W;
            s_y[r][c] = sig[(size_t)(rows0 + r) * W + c];
        }
        __syncthreads();
        // Slopes, once per row element (reference's exact formulas).
        for (int idx = tid; idx < rcnt * W; idx += 256) {
            int r = idx / W, c = idx - r * W;
            float m;
            if (c == 0)          m = s_y[r][1] - s_y[r][0];
            else if (c == W - 1) m = s_y[r][W - 1] - s_y[r][W - 2];
            else                 m = 0.5f * (s_y[r][c + 1] - s_y[r][c - 1]);
            s_m[r][c] = m;
        }
        // (s_m writes are ordered before eval by the weight-prelude sync below)

        for (int qb = 0; qb < Nx; qb += P1_QCH) {
            const int qcnt = min(P1_QCH, Nx - qb);
            for (int q = tid; q < qcnt; q += 256)
                hermite_h(xs[qb + q], W, &s_ix[q], &s_hx[q]);
            __syncthreads();

            for (int q0 = 0; q0 < qcnt; q0 += 256) {
                int q = q0 + tid;
                if (q < qcnt) {
                    int    I = s_ix[q];
                    float4 h = s_hx[q];
                    #pragma unroll
                    for (int r = 0; r < P1_ROWS; r++) {
                        if (r < rcnt) {
                            float ylo = s_y[r][I];
                            float mlo = s_m[r][I];
                            float yhi = s_y[r][I + 1];
                            float mhi = s_m[r][I + 1];
                            g_tmp[(size_t)(rows0 + r) * Nx + (qb + q)] =
                                h.x * ylo + h.y * mlo + h.z * yhi + h.w * mhi;
                        }
                    }
                }
            }
            __syncthreads();
        }
    } else {                               // gmem fallback (never hit at W=512)
        for (int qb = 0; qb < Nx; qb += P1_QCH) {
            const int qcnt = min(P1_QCH, Nx - qb);
            for (int q = tid; q < qcnt; q += 256)
                hermite_h(xs[qb + q], W, &s_ix[q], &s_hx[q]);
            __syncthreads();
            for (int r = 0; r < rcnt; r++) {
                const float* rp = sig + (size_t)(rows0 + r) * W;
                for (int q = tid; q < qcnt; q += 256) {
                    int    I = s_ix[q];
                    float4 h = s_hx[q];
                    float ym  = rp[max(I - 1, 0)];
                    float ylo = rp[I];
                    float yhi = rp[I + 1];
                    float yp  = rp[min(I + 2, W - 1)];
                    float mlo = (I == 0)     ? (yhi - ylo) : 0.5f * (yhi - ym);
                    float mhi = (I == W - 2) ? (yhi - ylo) : 0.5f * (yp - ylo);
                    g_tmp[(size_t)(rows0 + r) * Nx + (qb + q)] =
                        h.x * ylo + h.y * mlo + h.z * yhi + h.w * mhi;
                }
            }
            __syncthreads();
        }
    }
}

// Literal hermite combine — byte-identical expressions to the passing kernel.
__device__ __forceinline__ float4 eval4(float4 n0, float4 n1, float4 n2, float4 n3,
                                        float4 h, bool loE, bool hiE) {
    float4 o;
    {
        float mlo = loE ? (n2.x - n1.x) : 0.5f * (n2.x - n0.x);
        float mhi = hiE ? (n2.x - n1.x) : 0.5f * (n3.x - n1.x);
        o.x = h.x * n1.x + h.y * mlo + h.z * n2.x + h.w * mhi;
    }
    {
        float mlo = loE ? (n2.y - n1.y) : 0.5f * (n2.y - n0.y);
        float mhi = hiE ? (n2.y - n1.y) : 0.5f * (n3.y - n1.y);
        o.y = h.x * n1.y + h.y * mlo + h.z * n2.y + h.w * mhi;
    }
    {
        float mlo = loE ? (n2.z - n1.z) : 0.5f * (n2.z - n0.z);
        float mhi = hiE ? (n2.z - n1.z) : 0.5f * (n3.z - n1.z);
        o.z = h.x * n1.z + h.y * mlo + h.z * n2.z + h.w * mhi;
    }
    {
        float mlo = loE ? (n2.w - n1.w) : 0.5f * (n2.w - n0.w);
        float mhi = hiE ? (n2.w - n1.w) : 0.5f * (n3.w - n1.w);
        o.w = h.x * n1.w + h.y * mlo + h.z * n2.w + h.w * mhi;
    }
    return o;
}

// Pass 2: exact R11 champion. One thread = one float4 column x P2_G qy.
// Sorted ys => window shift d = I - Iprev >= 0; warp-uniform switch on
// d in {0,1,2,else}.
__global__ __launch_bounds__(256) void k_pass2(float* __restrict__ out,
                                               const float* __restrict__ ys,
                                               int H, int Nx, int Ny) {
    __shared__ int    s_iy[P2_G];
    __shared__ float4 s_hy[P2_G];

    const int nx4 = Nx >> 2;
    const int qy0 = blockIdx.x * P2_G;
    const int b   = blockIdx.y;

    if (threadIdx.x < P2_G && qy0 + threadIdx.x < Ny)
        hermite_h(ys[qy0 + threadIdx.x], H, &s_iy[threadIdx.x], &s_hy[threadIdx.x]);
    __syncthreads();

    const float4* tp = reinterpret_cast<const float4*>(g_tmp) + (size_t)b * H * nx4;
    float4* op = reinterpret_cast<float4*>(out) + (size_t)b * Ny * nx4;

    for (int qx4 = threadIdx.x; qx4 < nx4; qx4 += blockDim.x) {
        int iPrev = -0x40000000, r3Prev = -1;
        float4 z = make_float4(0.f, 0.f, 0.f, 0.f);
        float4 v0 = z, v1 = z, v2 = z, v3 = z;

        #pragma unroll
        for (int g = 0; g < P2_G; g++) {
            int qy = qy0 + g;
            if (qy >= Ny) break;
            int    I = s_iy[g];
            float4 h = s_hy[g];
            int R2 = I + 1;
            int R3 = min(I + 2, H - 1);
            int d  = I - iPrev;

            float4 n0, n1, n2, n3;
            if (d == 0) {
                n0 = v0; n1 = v1; n2 = v2; n3 = v3;
            } else if (d == 1) {
                n0 = v1; n1 = v2; n2 = v3;
                n3 = (R3 == r3Prev) ? v3 : tp[(size_t)R3 * nx4 + qx4];
            } else if (d == 2) {
                n0 = v2; n1 = v3;
                n2 = tp[(size_t)R2 * nx4 + qx4];
                n3 = (R3 == R2) ? n2 : tp[(size_t)R3 * nx4 + qx4];
            } else {
                int R0 = max(I - 1, 0);
                n0 = tp[(size_t)R0 * nx4 + qx4];
                n1 = tp[(size_t)I  * nx4 + qx4];
                n2 = tp[(size_t)R2 * nx4 + qx4];
                n3 = (R3 == R2) ? n2 : tp[(size_t)R3 * nx4 + qx4];
            }

            float4 o = eval4(n0, n1, n2, n3, h, I == 0, I == H - 2);
            __stcs(&op[(size_t)qy * nx4 + qx4], o);   // streaming: protect g_tmp in L2

            iPrev = I; r3Prev = R3;
            v0 = n0; v1 = n1; v2 = n2; v3 = n3;
        }
    }
}

extern "C" void kernel_launch(void* const* d_in, const int* in_sizes, int n_in,
                              void* d_out, int out_size) {
    const float* sig = (const float*)d_in[0];
    // d_in[1] = x1 (arange, dx=1), d_in[2] = x2 (arange, dx=1)
    const float* xs  = (const float*)d_in[3];
    const float* ys  = (const float*)d_in[4];

    int W  = in_sizes[1];
    int H  = in_sizes[2];
    int Nx = in_sizes[3];
    int Ny = in_sizes[4];
    int B  = in_sizes[0] / (W * H);
    int nRows = B * H;

    k_pass1<<<(nRows + P1_ROWS - 1) / P1_ROWS, 256>>>(sig, xs, W, Nx, nRows);

    dim3 g2((Ny + P2_G - 1) / P2_G, B);
    k_pass2<<<g2, 256>>>((float*)d_out, ys, H, Nx, Ny);
}

// round 17
// speedup vs baseline: 1.1784x; 1.1784x over previous
#include <cuda_runtime.h>

// ---------------------------------------------------------------------------
// CubicHermite2d — two-pass cubic Hermite (dx = 1).
//   result = h00*y[I] + h10*m[I] + h01*y[I+1] + h11*m[I+1]
//   m[0] = y1-y0; m[N-1] = y[N-1]-y[N-2]; m[i] = 0.5*(y[i+1]-y[i-1])
//   I = clamp(ceil(v)-1, 0, N-2)   == searchsorted(x0[1:-1], v, 'left')
// R11 champion + ADDRESSING DIET (no numeric/layout changes):
//   pass1: rcnt==8 specialized unrolled path, incremental store pointer
//          (kills the per-row 64-bit address IMAD chains R14's profile
//          showed dominating the issue budget).
//   pass2: int32 tap-index arithmetic; warp-uniform SHIFT dedup over sorted
//          qy (d in {0,1,2,else}), P2_G=16, __stcs stores.
// ---------------------------------------------------------------------------

#define TMP_ELEMS (32u * 512u * 1024u)   // B*H*Nx intermediate [B*H, Nx]
#define P1_ROWS 8
#define P1_WMAX 512
#define P1_QCH  1024
#define P2_G    16

__device__ float g_tmp[TMP_ELEMS];

__device__ __forceinline__ void hermite_h(float v, int N, int* Iout, float4* hout) {
    int I = (int)ceilf(v) - 1;          // searchsorted-left on arange
    I = max(0, min(I, N - 2));
    float t  = v - (float)I;
    float t2 = t * t;
    float t3 = t2 * t;
    *Iout = I;
    *hout = make_float4(1.0f - 3.0f * t2 + 2.0f * t3,   // h00
                        t - 2.0f * t2 + t3,             // h10
                        3.0f * t2 - 2.0f * t3,          // h01
                        t3 - t2);                       // h11
}

// One x-eval, identical expressions to R11.
__device__ __forceinline__ float evalx(const float s[P1_ROWS][P1_WMAX + 1], int r,
                                       int I, float4 h, int cm, int cp,
                                       bool xlo, bool xhi) {
    float ym  = s[r][cm];
    float ylo = s[r][I];
    float yhi = s[r][I + 1];
    float yp  = s[r][cp];
    float mlo = xlo ? (yhi - ylo) : 0.5f * (yhi - ym);
    float mhi = xhi ? (yhi - ylo) : 0.5f * (yp - ylo);
    return h.x * ylo + h.y * mlo + h.z * yhi + h.w * mhi;
}

// Pass 1: block = P1_ROWS consecutive (b,h) rows in smem; weights computed
// once per block into smem (R11-proven). Store addressing is incremental.
__global__ __launch_bounds__(256) void k_pass1(const float* __restrict__ sig,
                                               const float* __restrict__ xs,
                                               int W, int Nx, int nRows) {
    __shared__ float  s[P1_ROWS][P1_WMAX + 1];
    __shared__ int    s_ix[P1_QCH];
    __shared__ float4 s_hx[P1_QCH];

    const int tid   = threadIdx.x;
    const int rows0 = blockIdx.x * P1_ROWS;
    const int rcnt  = min(P1_ROWS, nRows - rows0);
    const bool full = (rcnt == P1_ROWS);

    if (W <= P1_WMAX) {
        for (int idx = tid; idx < rcnt * W; idx += 256) {
            int r = idx / W, c = idx - r * W;
            s[r][c] = sig[(size_t)(rows0 + r) * W + c];
        }
        for (int qb = 0; qb < Nx; qb += P1_QCH) {
            const int qcnt = min(P1_QCH, Nx - qb);
            for (int q = tid; q < qcnt; q += 256)
                hermite_h(xs[qb + q], W, &s_ix[q], &s_hx[q]);
            __syncthreads();

            for (int q0 = 0; q0 < qcnt; q0 += 256) {
                int q = q0 + tid;
                if (q < qcnt) {
                    int    I = s_ix[q];
                    float4 h = s_hx[q];
                    bool xlo = (I == 0);
                    bool xhi = (I == W - 2);
                    int cm = max(I - 1, 0);
                    int cp = min(I + 2, W - 1);
                    float* p = g_tmp + (size_t)rows0 * Nx + (qb + q);
                    if (full) {
                        #pragma unroll
                        for (int r = 0; r < P1_ROWS; r++) {
                            *p = evalx(s, r, I, h, cm, cp, xlo, xhi);
                            p += Nx;
                        }
                    } else {
                        for (int r = 0; r < rcnt; r++) {
                            *p = evalx(s, r, I, h, cm, cp, xlo, xhi);
                            p += Nx;
                        }
                    }
                }
            }
            __syncthreads();
        }
    } else {                               // gmem fallback (never hit at W=512)
        for (int qb = 0; qb < Nx; qb += P1_QCH) {
            const int qcnt = min(P1_QCH, Nx - qb);
            for (int q = tid; q < qcnt; q += 256)
                hermite_h(xs[qb + q], W, &s_ix[q], &s_hx[q]);
            __syncthreads();
            for (int r = 0; r < rcnt; r++) {
                const float* rp = sig + (size_t)(rows0 + r) * W;
                for (int q = tid; q < qcnt; q += 256) {
                    int    I = s_ix[q];
                    float4 h = s_hx[q];
                    float ym  = rp[max(I - 1, 0)];
                    float ylo = rp[I];
                    float yhi = rp[I + 1];
                    float yp  = rp[min(I + 2, W - 1)];
                    float mlo = (I == 0)     ? (yhi - ylo) : 0.5f * (yhi - ym);
                    float mhi = (I == W - 2) ? (yhi - ylo) : 0.5f * (yp - ylo);
                    g_tmp[(size_t)(rows0 + r) * Nx + (qb + q)] =
                        h.x * ylo + h.y * mlo + h.z * yhi + h.w * mhi;
                }
            }
            __syncthreads();
        }
    }
}

// Literal hermite combine — byte-identical expressions to the passing kernel.
__device__ __forceinline__ float4 eval4(float4 n0, float4 n1, float4 n2, float4 n3,
                                        float4 h, bool loE, bool hiE) {
    float4 o;
    {
        float mlo = loE ? (n2.x - n1.x) : 0.5f * (n2.x - n0.x);
        float mhi = hiE ? (n2.x - n1.x) : 0.5f * (n3.x - n1.x);
        o.x = h.x * n1.x + h.y * mlo + h.z * n2.x + h.w * mhi;
    }
    {
        float mlo = loE ? (n2.y - n1.y) : 0.5f * (n2.y - n0.y);
        float mhi = hiE ? (n2.y - n1.y) : 0.5f * (n3.y - n1.y);
        o.y = h.x * n1.y + h.y * mlo + h.z * n2.y + h.w * mhi;
    }
    {
        float mlo = loE ? (n2.z - n1.z) : 0.5f * (n2.z - n0.z);
        float mhi = hiE ? (n2.z - n1.z) : 0.5f * (n3.z - n1.z);
        o.z = h.x * n1.z + h.y * mlo + h.z * n2.z + h.w * mhi;
    }
    {
        float mlo = loE ? (n2.w - n1.w) : 0.5f * (n2.w - n0.w);
        float mhi = hiE ? (n2.w - n1.w) : 0.5f * (n3.w - n1.w);
        o.w = h.x * n1.w + h.y * mlo + h.z * n2.w + h.w * mhi;
    }
    return o;
}

// Pass 2: R11 champion with int32 tap-index arithmetic (all intra-batch
// offsets < 2^18). One thread = one float4 column x P2_G qy. Sorted ys =>
// window shift d = I - Iprev >= 0; warp-uniform switch on d in {0,1,2,else}.
__global__ __launch_bounds__(256) void k_pass2(float* __restrict__ out,
                                               const float* __restrict__ ys,
                                               int H, int Nx, int Ny) {
    __shared__ int    s_iy[P2_G];
    __shared__ float4 s_hy[P2_G];

    const int nx4 = Nx >> 2;
    const int qy0 = blockIdx.x * P2_G;
    const int b   = blockIdx.y;

    if (threadIdx.x < P2_G && qy0 + threadIdx.x < Ny)
        hermite_h(ys[qy0 + threadIdx.x], H, &s_iy[threadIdx.x], &s_hy[threadIdx.x]);
    __syncthreads();

    const float4* tp = reinterpret_cast<const float4*>(g_tmp) + (size_t)b * H * nx4;
    float4* op = reinterpret_cast<float4*>(out) + (size_t)b * Ny * nx4;

    for (int qx4 = threadIdx.x; qx4 < nx4; qx4 += blockDim.x) {
        int iPrev = -0x40000000, r3Prev = -1;
        float4 z = make_float4(0.f, 0.f, 0.f, 0.f);
        float4 v0 = z, v1 = z, v2 = z, v3 = z;

        #pragma unroll
        for (int g = 0; g < P2_G; g++) {
            int qy = qy0 + g;
            if (qy >= Ny) break;
            int    I = s_iy[g];
            float4 h = s_hy[g];
            int R2 = I + 1;
            int R3 = min(I + 2, H - 1);
            int d  = I - iPrev;

            float4 n0, n1, n2, n3;
            if (d == 0) {
                n0 = v0; n1 = v1; n2 = v2; n3 = v3;
            } else if (d == 1) {
                n0 = v1; n1 = v2; n2 = v3;
                n3 = (R3 == r3Prev) ? v3 : tp[R3 * nx4 + qx4];
            } else if (d == 2) {
                n0 = v2; n1 = v3;
                n2 = tp[R2 * nx4 + qx4];
                n3 = (R3 == R2) ? n2 : tp[R3 * nx4 + qx4];
            } else {
                int R0 = max(I - 1, 0);
                n0 = tp[R0 * nx4 + qx4];
                n1 = tp[I  * nx4 + qx4];
                n2 = tp[R2 * nx4 + qx4];
                n3 = (R3 == R2) ? n2 : tp[R3 * nx4 + qx4];
            }

            float4 o = eval4(n0, n1, n2, n3, h, I == 0, I == H - 2);
            __stcs(&op[qy * nx4 + qx4], o);   // streaming: protect g_tmp in L2

            iPrev = I; r3Prev = R3;
            v0 = n0; v1 = n1; v2 = n2; v3 = n3;
        }
    }
}

extern "C" void kernel_launch(void* const* d_in, const int* in_sizes, int n_in,
                              void* d_out, int out_size) {
    const float* sig = (const float*)d_in[0];
    // d_in[1] = x1 (arange, dx=1), d_in[2] = x2 (arange, dx=1)
    const float* xs  = (const float*)d_in[3];
    const float* ys  = (const float*)d_in[4];

    int W  = in_sizes[1];
    int H  = in_sizes[2];
    int Nx = in_sizes[3];
    int Ny = in_sizes[4];
    int B  = in_sizes[0] / (W * H);
    int nRows = B * H;

    k_pass1<<<(nRows + P1_ROWS - 1) / P1_ROWS, 256>>>(sig, xs, W, Nx, nRows);

    dim3 g2((Ny + P2_G - 1) / P2_G, B);
    k_pass2<<<g2, 256>>>((float*)d_out, ys, H, Nx, Ny);
}